// round 10
// baseline (speedup 1.0000x reference)
#include <cuda_runtime.h>
#include <cstdint>

#define BB 16
#define HH 1024
#define WW 1024
#define WORDS 32                    // uint32 words per row
#define HW (HH * WW)
#define NPIX (BB * HW)
#define NWORDS (BB * HH * WORDS)

#define NBLK 444                    // 148 SMs x 3 blocks, co-resident
#define NTHR 256
#define NTHREADS (NBLK * NTHR)
#define NWARPS (NTHREADS / 32)

#define ITROWS 4                    // rows per work item
#define ITEMS ((BB * HH) / ITROWS)  // 4096 items

__device__ unsigned int g_tbits[NWORDS];   // packed target bits (2 MiB)
__device__ unsigned long long g_ecount;
__device__ double g_A;
__device__ double g_B;
__device__ unsigned g_done;
__device__ unsigned g_c1;
__device__ volatile unsigned g_f1;

__device__ __forceinline__ float ex2f(float x) {
    float r; asm("ex2.approx.f32 %0, %1;" : "=f"(r) : "f"(x)); return r;
}

__global__ void __launch_bounds__(NTHR, 3)
k_fused(const float* __restrict__ s0, const float* __restrict__ s1,
        const int* __restrict__ tgt, float* __restrict__ out) {
    __shared__ unsigned se[ITROWS * WORDS];  // edge bits for current item
    __shared__ float sA[NTHR];
    __shared__ float sB[NTHR];
    __shared__ unsigned s_cnt;

    const int tid   = threadIdx.x;
    const int lane  = tid & 31;
    const int gwarp = (blockIdx.x * NTHR + tid) >> 5;

    if (tid == 0) s_cnt = 0;

    // ---------- Phase 1: pack target bits (grid-strided, balanced) ---------
    for (int w = gwarp; w < NPIX / 128; w += NWARPS) {
        int base = w * 128;
        int t0 = tgt[base + lane];
        int t1 = tgt[base + 32 + lane];
        int t2 = tgt[base + 64 + lane];
        int t3 = tgt[base + 96 + lane];
        unsigned b0 = __ballot_sync(0xffffffffu, t0 != 0);
        unsigned b1 = __ballot_sync(0xffffffffu, t1 != 0);
        unsigned b2 = __ballot_sync(0xffffffffu, t2 != 0);
        unsigned b3 = __ballot_sync(0xffffffffu, t3 != 0);
        if (lane == 0)
            *(uint4*)&g_tbits[w * 4] = make_uint4(b0, b1, b2, b3);
    }

    // ---------- Grid barrier -----------------------------------------------
    __syncthreads();
    if (tid == 0) {
        __threadfence();
        if (atomicAdd(&g_c1, 1u) == NBLK - 1) g_f1 = 1u;
        else while (g_f1 == 0u) __nanosleep(32);
        __threadfence();
    }
    __syncthreads();

    // ---------- Phase 2: items of 4 rows, statically strided ---------------
    float accA = 0.f, accB = 0.f;
    unsigned ecnt = 0;
    const float LOG2E = 1.4426950408889634f;

    const int rsub = tid >> 7;               // phase-C row within pair
    const int c8   = (tid & 127) * 8;        // 8-px column
    const int wj8  = c8 >> 5;
    const int sh8  = c8 & 31;

    for (int it = blockIdx.x; it < ITEMS; it += NBLK) {
        int bimg = it >> 8;                  // item / (HH/ITROWS)
        int r0   = (it & 255) * ITROWS;
        int wbase = (bimg * HH + r0) * WORDS;   // g_tbits word base of row r0

        __syncthreads();                     // protect se from prior readers

        // ---- edge words: 128 threads, one word each (4 rows x 32 words) ---
        if (tid < ITROWS * WORDS) {
            int rl = tid >> 5, j = tid & 31;
            int gr0 = r0 + rl;
            unsigned orL = 0, orM = 0, orR = 0;
            unsigned anL = ~0u, anM = ~0u, anR = ~0u;
            unsigned T = 0;
            #pragma unroll
            for (int d = 0; d < 11; ++d) {
                int gr = gr0 + d - 5;
                unsigned wl = 0, wm = 0, wr = 0;
                if ((unsigned)gr < HH) {
                    const unsigned* p = g_tbits + (bimg * HH + gr) * WORDS;
                    wm = p[j];
                    wl = (j > 0)  ? p[j - 1] : 0u;
                    wr = (j < 31) ? p[j + 1] : 0u;
                }
                if (d == 5) T = wm;
                orL |= wl; orM |= wm; orR |= wr;
                anL &= wl; anM &= wm; anR &= wr;
            }
            unsigned nL = ~anL, nM = ~anM, nR = ~anR;
            unsigned any1 = orM, any0 = nM;
            #pragma unroll
            for (int s = 1; s <= 5; s++) {
                any1 |= __funnelshift_r(orM, orR, s);
                any1 |= __funnelshift_l(orL, orM, s);
                any0 |= __funnelshift_r(nM, nR, s);
                any0 |= __funnelshift_l(nL, nM, s);
            }
            unsigned e = (T & any0) | (~T & any1);
            se[tid] = e;
            ecnt += __popc(e);
        }
        __syncthreads();

        // ---- stream scores: 2 iterations x (2 rows x 8 px/thread) ---------
        size_t pixbase = (size_t)bimg * 2 * HW + (size_t)(r0 + rsub) * WW + c8;
        const float* p00 = s0 + pixbase;
        const float* p01 = p00 + HW;
        const float* p10 = s1 + pixbase;
        const float* p11 = p10 + HW;

        #pragma unroll
        for (int i = 0; i < ITROWS / 2; ++i) {
            size_t off = (size_t)(i * 2) * WW;
            float4 a0  = *(const float4*)(p00 + off);
            float4 a0b = *(const float4*)(p00 + off + 4);
            float4 a1  = *(const float4*)(p01 + off);
            float4 a1b = *(const float4*)(p01 + off + 4);
            float4 c0  = *(const float4*)(p10 + off);
            float4 c0b = *(const float4*)(p10 + off + 4);
            float4 c1  = *(const float4*)(p11 + off);
            float4 c1b = *(const float4*)(p11 + off + 4);

            int rl = i * 2 + rsub;
            unsigned tw = g_tbits[wbase + rl * WORDS + wj8] >> sh8;
            unsigned ew = se[rl * WORDS + wj8] >> sh8;
            unsigned ntw = ~tw;

            float x0[8] = {a0.x, a0.y, a0.z, a0.w, a0b.x, a0b.y, a0b.z, a0b.w};
            float x1[8] = {a1.x, a1.y, a1.z, a1.w, a1b.x, a1b.y, a1b.z, a1b.w};
            float y0[8] = {c0.x, c0.y, c0.z, c0.w, c0b.x, c0b.y, c0b.z, c0b.w};
            float y1[8] = {c1.x, c1.y, c1.z, c1.w, c1b.x, c1b.y, c1b.z, c1b.w};

            #pragma unroll
            for (int k = 0; k < 8; k++) {
                unsigned sflip = (ntw << (31 - k)) & 0x80000000u;
                int      emask = ((int)(ew << (31 - k))) >> 31;

                float d2 = (x1[k] - x0[k]) * LOG2E;
                float u  = __int_as_float(__float_as_int(d2) ^ sflip);
                float z  = ex2f(-fabsf(u));
                float sp = fmaxf(-u, 0.f) + __log2f(1.f + z);

                float e2 = (y1[k] - y0[k]) * LOG2E;
                float v  = __int_as_float(__float_as_int(e2) ^ sflip);
                float z2 = ex2f(-fabsf(v));
                float sq = fmaxf(-v, 0.f) + __log2f(1.f + z2);

                accA += sp + 0.5f * sq;
                float Bt = (0.5f * sp + u) + 0.5f * (0.5f * sq + v);
                accB += __int_as_float(__float_as_int(Bt) & emask);
            }
        }
    }

    // ---------- Block reduction + global accumulation ----------------------
    ecnt = __reduce_add_sync(0xffffffffu, ecnt);
    if (lane == 0 && ecnt) atomicAdd(&s_cnt, ecnt);

    sA[tid] = accA;
    sB[tid] = accB;
    __syncthreads();
    #pragma unroll
    for (int s = NTHR / 2; s > 0; s >>= 1) {
        if (tid < s) { sA[tid] += sA[tid + s]; sB[tid] += sB[tid + s]; }
        __syncthreads();
    }

    if (tid == 0) {
        atomicAdd(&g_A, (double)sA[0]);
        atomicAdd(&g_B, (double)sB[0]);
        atomicAdd(&g_ecount, (unsigned long long)s_cnt);
        __threadfence();
        unsigned done = atomicAdd(&g_done, 1u);
        if (done == NBLK - 1) {
            const double LN2 = 0.6931471805599453;
            double N = (double)NPIX;
            double a = (double)g_ecount / N;
            if (a > 0.2) a = 0.2;
            out[0] = (float)((g_A + a * g_B) * LN2 / N);
            // reset ALL state for the next graph replay
            g_A = 0.0; g_B = 0.0; g_ecount = 0ull;
            g_c1 = 0u; g_f1 = 0u;
            __threadfence();
            g_done = 0u;
        }
    }
}

// ---------------------------------------------------------------------------
extern "C" void kernel_launch(void* const* d_in, const int* in_sizes, int n_in,
                              void* d_out, int out_size) {
    int ti = 0;
    for (int i = 1; i < n_in; i++)
        if (in_sizes[i] < in_sizes[ti]) ti = i;
    const float* s0 = nullptr;
    const float* s1 = nullptr;
    for (int i = 0; i < n_in; i++) {
        if (i == ti) continue;
        if (!s0) s0 = (const float*)d_in[i];
        else     s1 = (const float*)d_in[i];
    }
    const int* tgt = (const int*)d_in[ti];

    k_fused<<<NBLK, NTHR>>>(s0, s1, tgt, (float*)d_out);
}

// round 11
// speedup vs baseline: 1.5454x; 1.5454x over previous
#include <cuda_runtime.h>
#include <cstdint>

#define BB 16
#define HH 1024
#define WW 1024
#define WORDS 32                    // uint32 words per row
#define HW (HH * WW)
#define NPIX (BB * HW)
#define NWORDS (BB * HH * WORDS)

#define NBLK 592                    // 148 SMs x 4 blocks, co-resident
#define NTHR 256
#define NTHREADS (NBLK * NTHR)
#define NWARPS (NTHREADS / 32)

#define PAIRS (BB * HH / 2)         // 8192 two-row items

__device__ unsigned int g_tbits[NWORDS];   // packed target bits (2 MiB)
__device__ unsigned int g_ebits[NWORDS];   // packed edge bits   (2 MiB)
__device__ unsigned long long g_ecount;
__device__ double g_A;
__device__ double g_B;
__device__ unsigned g_done;
__device__ unsigned g_c1, g_c2;
__device__ volatile unsigned g_f1, g_f2;

__device__ __forceinline__ float ex2f(float x) {
    float r; asm("ex2.approx.f32 %0, %1;" : "=f"(r) : "f"(x)); return r;
}

__device__ __forceinline__ void gbar(unsigned* cnt, volatile unsigned* flag) {
    __syncthreads();
    if (threadIdx.x == 0) {
        __threadfence();
        if (atomicAdd(cnt, 1u) == NBLK - 1) *flag = 1u;
        else while (*flag == 0u) __nanosleep(32);
        __threadfence();
    }
    __syncthreads();
}

__global__ void __launch_bounds__(NTHR, 4)
k_fused(const float* __restrict__ s0, const float* __restrict__ s1,
        const int* __restrict__ tgt, float* __restrict__ out) {
    __shared__ float sA[NTHR];
    __shared__ float sB[NTHR];

    const int tid   = threadIdx.x;
    const int lane  = tid & 31;
    const int gtid  = blockIdx.x * NTHR + tid;
    const int gwarp = gtid >> 5;

    // ---------- Phase 1: pack target bits (grid-strided, balanced) ---------
    for (int w = gwarp; w < NPIX / 128; w += NWARPS) {
        int base = w * 128;
        int t0 = tgt[base + lane];
        int t1 = tgt[base + 32 + lane];
        int t2 = tgt[base + 64 + lane];
        int t3 = tgt[base + 96 + lane];
        unsigned b0 = __ballot_sync(0xffffffffu, t0 != 0);
        unsigned b1 = __ballot_sync(0xffffffffu, t1 != 0);
        unsigned b2 = __ballot_sync(0xffffffffu, t2 != 0);
        unsigned b3 = __ballot_sync(0xffffffffu, t3 != 0);
        if (lane == 0)
            *(uint4*)&g_tbits[w * 4] = make_uint4(b0, b1, b2, b3);
    }

    gbar(&g_c1, &g_f1);

    // ---------- Phase 2: edge words -> g_ebits (grid-strided) --------------
    unsigned ecnt = 0;
    for (int idx = gtid; idx < NWORDS; idx += NTHREADS) {
        int j   = idx & (WORDS - 1);
        int row = idx >> 5;                  // b*H + y
        int y   = row & (HH - 1);
        const unsigned* rb = g_tbits + (row - y) * WORDS;

        unsigned orL = 0, orM = 0, orR = 0;
        unsigned anL = ~0u, anM = ~0u, anR = ~0u;
        #pragma unroll
        for (int d = -5; d <= 5; ++d) {
            int r = y + d;
            unsigned wl = 0, wm = 0, wr = 0;
            if ((unsigned)r < HH) {
                const unsigned* p = rb + r * WORDS;
                wm = p[j];
                wl = (j > 0)  ? p[j - 1] : 0u;
                wr = (j < 31) ? p[j + 1] : 0u;
            }
            orL |= wl; orM |= wm; orR |= wr;
            anL &= wl; anM &= wm; anR &= wr;
        }
        unsigned nL = ~anL, nM = ~anM, nR = ~anR;
        unsigned any1 = orM, any0 = nM;
        #pragma unroll
        for (int s = 1; s <= 5; s++) {
            any1 |= __funnelshift_r(orM, orR, s);
            any1 |= __funnelshift_l(orL, orM, s);
            any0 |= __funnelshift_r(nM, nR, s);
            any0 |= __funnelshift_l(nL, nM, s);
        }
        unsigned T = g_tbits[idx];
        unsigned e = (T & any0) | (~T & any1);
        g_ebits[idx] = e;
        ecnt += __popc(e);
    }

    gbar(&g_c2, &g_f2);

    // ---------- Phase 3: pure streaming, no syncs, no smem -----------------
    // log2-domain: u = (x1-x0)*log2e sign-flipped so target class positive:
    //   -logp_t/ln2             = sp2(-u) = max(-u,0)+lg2(1+ex2(-|u|))
    //   (0.5*logp_t-logp_o)/ln2 = 0.5*sp2(-u) + u
    float accA = 0.f, accB = 0.f;
    {
        const float LOG2E = 1.4426950408889634f;
        const int rsub = tid >> 7;           // row within pair (0/1)
        const int c8   = (tid & 127) * 8;    // 8-px column
        const int wj8  = c8 >> 5;
        const int sh8  = c8 & 31;

        for (int it = blockIdx.x; it < PAIRS; it += NBLK) {
            int bimg = it >> 9;              // item / 512
            int row  = (it & 511) * 2 + rsub;
            int widx = (bimg * HH + row) * WORDS + wj8;

            size_t pixbase = (size_t)bimg * 2 * HW + (size_t)row * WW + c8;
            const float* p00 = s0 + pixbase;
            const float* p10 = s1 + pixbase;

            float4 a0  = __ldcs((const float4*)(p00));
            float4 a0b = __ldcs((const float4*)(p00 + 4));
            float4 a1  = __ldcs((const float4*)(p00 + HW));
            float4 a1b = __ldcs((const float4*)(p00 + HW + 4));
            float4 c0  = __ldcs((const float4*)(p10));
            float4 c0b = __ldcs((const float4*)(p10 + 4));
            float4 c1  = __ldcs((const float4*)(p10 + HW));
            float4 c1b = __ldcs((const float4*)(p10 + HW + 4));

            unsigned tw = g_tbits[widx] >> sh8;
            unsigned ew = g_ebits[widx] >> sh8;
            unsigned ntw = ~tw;

            float x0[8] = {a0.x, a0.y, a0.z, a0.w, a0b.x, a0b.y, a0b.z, a0b.w};
            float x1[8] = {a1.x, a1.y, a1.z, a1.w, a1b.x, a1b.y, a1b.z, a1b.w};
            float y0[8] = {c0.x, c0.y, c0.z, c0.w, c0b.x, c0b.y, c0b.z, c0b.w};
            float y1[8] = {c1.x, c1.y, c1.z, c1.w, c1b.x, c1b.y, c1b.z, c1b.w};

            #pragma unroll
            for (int k = 0; k < 8; k++) {
                unsigned sflip = (ntw << (31 - k)) & 0x80000000u;
                int      emask = ((int)(ew << (31 - k))) >> 31;

                float d2 = (x1[k] - x0[k]) * LOG2E;
                float u  = __int_as_float(__float_as_int(d2) ^ sflip);
                float z  = ex2f(-fabsf(u));
                float sp = fmaxf(-u, 0.f) + __log2f(1.f + z);

                float e2 = (y1[k] - y0[k]) * LOG2E;
                float v  = __int_as_float(__float_as_int(e2) ^ sflip);
                float z2 = ex2f(-fabsf(v));
                float sq = fmaxf(-v, 0.f) + __log2f(1.f + z2);

                accA += sp + 0.5f * sq;
                float Bt = (0.5f * sp + u) + 0.5f * (0.5f * sq + v);
                accB += __int_as_float(__float_as_int(Bt) & emask);
            }
        }
    }

    // ---------- Block reduction + global accumulation ----------------------
    ecnt = __reduce_add_sync(0xffffffffu, ecnt);

    sA[tid] = accA;
    sB[tid] = accB;
    __syncthreads();
    #pragma unroll
    for (int s = NTHR / 2; s > 0; s >>= 1) {
        if (tid < s) { sA[tid] += sA[tid + s]; sB[tid] += sB[tid + s]; }
        __syncthreads();
    }

    if (lane == 0 && ecnt)
        atomicAdd(&g_ecount, (unsigned long long)ecnt);

    if (tid == 0) {
        atomicAdd(&g_A, (double)sA[0]);
        atomicAdd(&g_B, (double)sB[0]);
        __threadfence();
        unsigned done = atomicAdd(&g_done, 1u);
        if (done == NBLK - 1) {
            const double LN2 = 0.6931471805599453;
            double N = (double)NPIX;
            double a = (double)g_ecount / N;
            if (a > 0.2) a = 0.2;
            out[0] = (float)((g_A + a * g_B) * LN2 / N);
            // reset ALL state for the next graph replay
            g_A = 0.0; g_B = 0.0; g_ecount = 0ull;
            g_c1 = 0u; g_f1 = 0u;
            g_c2 = 0u; g_f2 = 0u;
            __threadfence();
            g_done = 0u;
        }
    }
}

// ---------------------------------------------------------------------------
extern "C" void kernel_launch(void* const* d_in, const int* in_sizes, int n_in,
                              void* d_out, int out_size) {
    int ti = 0;
    for (int i = 1; i < n_in; i++)
        if (in_sizes[i] < in_sizes[ti]) ti = i;
    const float* s0 = nullptr;
    const float* s1 = nullptr;
    for (int i = 0; i < n_in; i++) {
        if (i == ti) continue;
        if (!s0) s0 = (const float*)d_in[i];
        else     s1 = (const float*)d_in[i];
    }
    const int* tgt = (const int*)d_in[ti];

    k_fused<<<NBLK, NTHR>>>(s0, s1, tgt, (float*)d_out);
}

// round 12
// speedup vs baseline: 1.5891x; 1.0283x over previous
#include <cuda_runtime.h>
#include <cstdint>

#define BB 16
#define HH 1024
#define WW 1024
#define WORDS 32                    // uint32 words per row
#define HW (HH * WW)
#define NPIX (BB * HW)
#define NWORDS (BB * HH * WORDS)

#define NBLK 592                    // 148 SMs x 4 blocks, co-resident
#define NTHR 256
#define NTHREADS (NBLK * NTHR)
#define NWARPS (NTHREADS / 32)

#define PAIRS (BB * HH / 2)         // 8192 two-row items

__device__ unsigned int g_tbits[NWORDS];   // packed target bits (2 MiB)
__device__ uint2        g_te[NWORDS];      // (tbits, ebits) interleaved (4 MiB)
__device__ unsigned long long g_ecount;
__device__ double g_A;
__device__ double g_B;
__device__ unsigned g_done;
__device__ unsigned g_c1, g_c2;
__device__ volatile unsigned g_f1, g_f2;

__device__ __forceinline__ float ex2f(float x) {
    float r; asm("ex2.approx.f32 %0, %1;" : "=f"(r) : "f"(x)); return r;
}

__device__ __forceinline__ void gbar(unsigned* cnt, volatile unsigned* flag) {
    __syncthreads();
    if (threadIdx.x == 0) {
        __threadfence();
        if (atomicAdd(cnt, 1u) == NBLK - 1) *flag = 1u;
        else while (*flag == 0u) __nanosleep(32);
        __threadfence();
    }
    __syncthreads();
}

__global__ void __launch_bounds__(NTHR, 4)
k_fused(const float* __restrict__ s0, const float* __restrict__ s1,
        const int* __restrict__ tgt, float* __restrict__ out) {
    __shared__ float sA[NTHR];
    __shared__ float sB[NTHR];

    const int tid   = threadIdx.x;
    const int lane  = tid & 31;
    const int gtid  = blockIdx.x * NTHR + tid;
    const int gwarp = gtid >> 5;

    // ---------- Phase 1: pack target bits (8 indep. 128B loads/warp-iter) --
    for (int w = gwarp; w < NPIX / 256; w += NWARPS) {
        int base = w * 256;
        int t0 = tgt[base + lane];
        int t1 = tgt[base + 32 + lane];
        int t2 = tgt[base + 64 + lane];
        int t3 = tgt[base + 96 + lane];
        int t4 = tgt[base + 128 + lane];
        int t5 = tgt[base + 160 + lane];
        int t6 = tgt[base + 192 + lane];
        int t7 = tgt[base + 224 + lane];
        unsigned b0 = __ballot_sync(0xffffffffu, t0 != 0);
        unsigned b1 = __ballot_sync(0xffffffffu, t1 != 0);
        unsigned b2 = __ballot_sync(0xffffffffu, t2 != 0);
        unsigned b3 = __ballot_sync(0xffffffffu, t3 != 0);
        unsigned b4 = __ballot_sync(0xffffffffu, t4 != 0);
        unsigned b5 = __ballot_sync(0xffffffffu, t5 != 0);
        unsigned b6 = __ballot_sync(0xffffffffu, t6 != 0);
        unsigned b7 = __ballot_sync(0xffffffffu, t7 != 0);
        if (lane == 0) {
            *(uint4*)&g_tbits[w * 8]     = make_uint4(b0, b1, b2, b3);
            *(uint4*)&g_tbits[w * 8 + 4] = make_uint4(b4, b5, b6, b7);
        }
    }

    gbar(&g_c1, &g_f1);

    // ---------- Phase 2: edge words -> g_te (grid-strided) -----------------
    unsigned ecnt = 0;
    for (int idx = gtid; idx < NWORDS; idx += NTHREADS) {
        int j   = idx & (WORDS - 1);
        int row = idx >> 5;                  // b*H + y
        int y   = row & (HH - 1);
        const unsigned* rb = g_tbits + (row - y) * WORDS;

        unsigned orL = 0, orM = 0, orR = 0;
        unsigned anL = ~0u, anM = ~0u, anR = ~0u;
        #pragma unroll
        for (int d = -5; d <= 5; ++d) {
            int r = y + d;
            unsigned wl = 0, wm = 0, wr = 0;
            if ((unsigned)r < HH) {
                const unsigned* p = rb + r * WORDS;
                wm = p[j];
                wl = (j > 0)  ? p[j - 1] : 0u;
                wr = (j < 31) ? p[j + 1] : 0u;
            }
            orL |= wl; orM |= wm; orR |= wr;
            anL &= wl; anM &= wm; anR &= wr;
        }
        unsigned nL = ~anL, nM = ~anM, nR = ~anR;
        unsigned any1 = orM, any0 = nM;
        #pragma unroll
        for (int s = 1; s <= 5; s++) {
            any1 |= __funnelshift_r(orM, orR, s);
            any1 |= __funnelshift_l(orL, orM, s);
            any0 |= __funnelshift_r(nM, nR, s);
            any0 |= __funnelshift_l(nL, nM, s);
        }
        unsigned T = g_tbits[idx];
        unsigned e = (T & any0) | (~T & any1);
        g_te[idx] = make_uint2(T, e);
        ecnt += __popc(e);
    }

    // ---------- Prefetch first item's scores, THEN barrier -----------------
    const float LOG2E = 1.4426950408889634f;
    const int rsub = tid >> 7;               // row within pair (0/1)
    const int c8   = (tid & 127) * 8;        // 8-px column
    const int wj8  = c8 >> 5;
    const int sh8  = c8 & 31;

    float accA = 0.f, accB = 0.f;

    {
        int it0 = blockIdx.x;                // first item (always < PAIRS)
        int bimg = it0 >> 9;
        int row  = (it0 & 511) * 2 + rsub;
        int widx = (bimg * HH + row) * WORDS + wj8;
        size_t pixbase = (size_t)bimg * 2 * HW + (size_t)row * WW + c8;
        const float* p00 = s0 + pixbase;
        const float* p10 = s1 + pixbase;

        // loads in flight across the barrier wait
        float4 a0  = __ldcs((const float4*)(p00));
        float4 a0b = __ldcs((const float4*)(p00 + 4));
        float4 a1  = __ldcs((const float4*)(p00 + HW));
        float4 a1b = __ldcs((const float4*)(p00 + HW + 4));
        float4 c0  = __ldcs((const float4*)(p10));
        float4 c0b = __ldcs((const float4*)(p10 + 4));
        float4 c1  = __ldcs((const float4*)(p10 + HW));
        float4 c1b = __ldcs((const float4*)(p10 + HW + 4));

        gbar(&g_c2, &g_f2);                  // t/e words become valid

        uint2 te = g_te[widx];
        unsigned tw = te.x >> sh8;
        unsigned ew = te.y >> sh8;
        unsigned ntw = ~tw;

        float x0[8] = {a0.x, a0.y, a0.z, a0.w, a0b.x, a0b.y, a0b.z, a0b.w};
        float x1[8] = {a1.x, a1.y, a1.z, a1.w, a1b.x, a1b.y, a1b.z, a1b.w};
        float y0[8] = {c0.x, c0.y, c0.z, c0.w, c0b.x, c0b.y, c0b.z, c0b.w};
        float y1[8] = {c1.x, c1.y, c1.z, c1.w, c1b.x, c1b.y, c1b.z, c1b.w};

        #pragma unroll
        for (int k = 0; k < 8; k++) {
            unsigned sflip = (ntw << (31 - k)) & 0x80000000u;
            int      emask = ((int)(ew << (31 - k))) >> 31;
            float d2 = (x1[k] - x0[k]) * LOG2E;
            float u  = __int_as_float(__float_as_int(d2) ^ sflip);
            float z  = ex2f(-fabsf(u));
            float sp = fmaxf(-u, 0.f) + __log2f(1.f + z);
            float e2 = (y1[k] - y0[k]) * LOG2E;
            float v  = __int_as_float(__float_as_int(e2) ^ sflip);
            float z2 = ex2f(-fabsf(v));
            float sq = fmaxf(-v, 0.f) + __log2f(1.f + z2);
            accA += sp + 0.5f * sq;
            float Bt = (0.5f * sp + u) + 0.5f * (0.5f * sq + v);
            accB += __int_as_float(__float_as_int(Bt) & emask);
        }
    }

    // ---------- Phase 3: remaining items, pure streaming -------------------
    for (int it = blockIdx.x + NBLK; it < PAIRS; it += NBLK) {
        int bimg = it >> 9;
        int row  = (it & 511) * 2 + rsub;
        int widx = (bimg * HH + row) * WORDS + wj8;

        size_t pixbase = (size_t)bimg * 2 * HW + (size_t)row * WW + c8;
        const float* p00 = s0 + pixbase;
        const float* p10 = s1 + pixbase;

        float4 a0  = __ldcs((const float4*)(p00));
        float4 a0b = __ldcs((const float4*)(p00 + 4));
        float4 a1  = __ldcs((const float4*)(p00 + HW));
        float4 a1b = __ldcs((const float4*)(p00 + HW + 4));
        float4 c0  = __ldcs((const float4*)(p10));
        float4 c0b = __ldcs((const float4*)(p10 + 4));
        float4 c1  = __ldcs((const float4*)(p10 + HW));
        float4 c1b = __ldcs((const float4*)(p10 + HW + 4));

        uint2 te = g_te[widx];
        unsigned tw = te.x >> sh8;
        unsigned ew = te.y >> sh8;
        unsigned ntw = ~tw;

        float x0[8] = {a0.x, a0.y, a0.z, a0.w, a0b.x, a0b.y, a0b.z, a0b.w};
        float x1[8] = {a1.x, a1.y, a1.z, a1.w, a1b.x, a1b.y, a1b.z, a1b.w};
        float y0[8] = {c0.x, c0.y, c0.z, c0.w, c0b.x, c0b.y, c0b.z, c0b.w};
        float y1[8] = {c1.x, c1.y, c1.z, c1.w, c1b.x, c1b.y, c1b.z, c1b.w};

        #pragma unroll
        for (int k = 0; k < 8; k++) {
            unsigned sflip = (ntw << (31 - k)) & 0x80000000u;
            int      emask = ((int)(ew << (31 - k))) >> 31;

            float d2 = (x1[k] - x0[k]) * LOG2E;
            float u  = __int_as_float(__float_as_int(d2) ^ sflip);
            float z  = ex2f(-fabsf(u));
            float sp = fmaxf(-u, 0.f) + __log2f(1.f + z);

            float e2 = (y1[k] - y0[k]) * LOG2E;
            float v  = __int_as_float(__float_as_int(e2) ^ sflip);
            float z2 = ex2f(-fabsf(v));
            float sq = fmaxf(-v, 0.f) + __log2f(1.f + z2);

            accA += sp + 0.5f * sq;
            float Bt = (0.5f * sp + u) + 0.5f * (0.5f * sq + v);
            accB += __int_as_float(__float_as_int(Bt) & emask);
        }
    }

    // ---------- Block reduction + global accumulation ----------------------
    ecnt = __reduce_add_sync(0xffffffffu, ecnt);

    sA[tid] = accA;
    sB[tid] = accB;
    __syncthreads();
    #pragma unroll
    for (int s = NTHR / 2; s > 0; s >>= 1) {
        if (tid < s) { sA[tid] += sA[tid + s]; sB[tid] += sB[tid + s]; }
        __syncthreads();
    }

    if (lane == 0 && ecnt)
        atomicAdd(&g_ecount, (unsigned long long)ecnt);

    if (tid == 0) {
        atomicAdd(&g_A, (double)sA[0]);
        atomicAdd(&g_B, (double)sB[0]);
        __threadfence();
        unsigned done = atomicAdd(&g_done, 1u);
        if (done == NBLK - 1) {
            const double LN2 = 0.6931471805599453;
            double N = (double)NPIX;
            double a = (double)g_ecount / N;
            if (a > 0.2) a = 0.2;
            out[0] = (float)((g_A + a * g_B) * LN2 / N);
            // reset ALL state for the next graph replay
            g_A = 0.0; g_B = 0.0; g_ecount = 0ull;
            g_c1 = 0u; g_f1 = 0u;
            g_c2 = 0u; g_f2 = 0u;
            __threadfence();
            g_done = 0u;
        }
    }
}

// ---------------------------------------------------------------------------
extern "C" void kernel_launch(void* const* d_in, const int* in_sizes, int n_in,
                              void* d_out, int out_size) {
    int ti = 0;
    for (int i = 1; i < n_in; i++)
        if (in_sizes[i] < in_sizes[ti]) ti = i;
    const float* s0 = nullptr;
    const float* s1 = nullptr;
    for (int i = 0; i < n_in; i++) {
        if (i == ti) continue;
        if (!s0) s0 = (const float*)d_in[i];
        else     s1 = (const float*)d_in[i];
    }
    const int* tgt = (const int*)d_in[ti];

    k_fused<<<NBLK, NTHR>>>(s0, s1, tgt, (float*)d_out);
}